// round 2
// baseline (speedup 1.0000x reference)
#include <cuda_runtime.h>
#include <cuda_bf16.h>

#define NBINS 15
#define MAINBLOCKS 1184
#define MAINTHREADS 256

// Global scratch (allocation-free): per-bin totals.
__device__ float g_cnt[NBINS];
__device__ float g_err[NBINS];
__device__ float g_su[NBINS];

__global__ void zero_scratch_kernel() {
    int t = threadIdx.x;
    if (t < NBINS) { g_cnt[t] = 0.0f; g_err[t] = 0.0f; g_su[t] = 0.0f; }
}

// Per-row computation: softmax collision entropy + hard error.
// Returns bin in [0,15) or -1 if invalid, u, err (0/1).
__device__ __forceinline__ void process_row(const float* __restrict__ r, int label,
                                            int& bin, float& u, unsigned& err) {
    float m = r[0];
    int am = 0;
#pragma unroll
    for (int j = 1; j < 10; j++) {
        if (r[j] > m) { m = r[j]; am = j; }   // strict > keeps first max (jnp.argmax)
    }
    float S = 0.0f, Q = 0.0f;
#pragma unroll
    for (int j = 0; j < 10; j++) {
        float e = exp2f((r[j] - m) * 1.4426950408889634f);
        S += e;
        Q += e * e;
    }
    float q = Q / (S * S);          // sum(p^2)
    u = -log2f(q + 1e-12f);
    err = (am != label) ? 1u : 0u;

    const float DELTA = (float)(1.0 / 15.0);
    int b = (int)floorf(u / DELTA);
    bool valid = (u >= 0.0f) && (u < 1.0f) && (b >= 0) && (b < NBINS);
    bin = valid ? b : -1;
}

__global__ __launch_bounds__(MAINTHREADS)
void uce_main_kernel(const float4* __restrict__ L4, const int2* __restrict__ lab2,
                     int P /* pairs */, int N) {
    // Register-resident per-thread bin accumulators.
    unsigned cep[NBINS];   // count (low 16) | err_count (high 16)
    float    su[NBINS];
#pragma unroll
    for (int j = 0; j < NBINS; j++) { cep[j] = 0u; su[j] = 0.0f; }

    const int stride = gridDim.x * blockDim.x;
    for (int p = blockIdx.x * blockDim.x + threadIdx.x; p < P; p += stride) {
        // 2 rows = 20 floats = 5 float4 (80B, 16B-aligned).
        float4 a0 = L4[5 * p + 0];
        float4 a1 = L4[5 * p + 1];
        float4 a2 = L4[5 * p + 2];
        float4 a3 = L4[5 * p + 3];
        float4 a4 = L4[5 * p + 4];
        int2 lb = lab2[p];

        float f[20] = {a0.x, a0.y, a0.z, a0.w,
                       a1.x, a1.y, a1.z, a1.w,
                       a2.x, a2.y, a2.z, a2.w,
                       a3.x, a3.y, a3.z, a3.w,
                       a4.x, a4.y, a4.z, a4.w};

        int b0, b1; float u0, u1; unsigned e0, e1;
        process_row(f,      lb.x, b0, u0, e0);
        process_row(f + 10, lb.y, b1, u1, e1);

        unsigned pk0 = 1u | (e0 << 16);
        unsigned pk1 = 1u | (e1 << 16);
#pragma unroll
        for (int j = 0; j < NBINS; j++) {
            if (b0 == j) { cep[j] += pk0; su[j] += u0; }
            if (b1 == j) { cep[j] += pk1; su[j] += u1; }
        }
    }

    // Tail sample if N is odd.
    if ((N & 1) && blockIdx.x == 0 && threadIdx.x == 0) {
        const float* Lf = (const float*)L4;
        const int* labf = (const int*)lab2;
        float f[10];
#pragma unroll
        for (int j = 0; j < 10; j++) f[j] = Lf[(long long)(N - 1) * 10 + j];
        int b; float u; unsigned e;
        process_row(f, labf[N - 1], b, u, e);
        unsigned pk = 1u | (e << 16);
#pragma unroll
        for (int j = 0; j < NBINS; j++) {
            if (b == j) { cep[j] += pk; su[j] += u; }
        }
    }

    // ---- Block reduction: warp shuffle -> smem -> global atomics ----
    __shared__ float    s_su[MAINTHREADS / 32][NBINS];
    __shared__ unsigned s_cep[MAINTHREADS / 32][NBINS];

    int lane = threadIdx.x & 31;
    int wid  = threadIdx.x >> 5;

#pragma unroll
    for (int j = 0; j < NBINS; j++) {
        float    s = su[j];
        unsigned c = cep[j];
#pragma unroll
        for (int off = 16; off > 0; off >>= 1) {
            s += __shfl_down_sync(0xFFFFFFFFu, s, off);
            c += __shfl_down_sync(0xFFFFFFFFu, c, off);
        }
        if (lane == 0) { s_su[wid][j] = s; s_cep[wid][j] = c; }
    }
    __syncthreads();

    if (threadIdx.x < NBINS) {
        int j = threadIdx.x;
        float    s = 0.0f;
        unsigned cnt = 0u, er = 0u;
#pragma unroll
        for (int w = 0; w < MAINTHREADS / 32; w++) {
            s += s_su[w][j];
            unsigned c = s_cep[w][j];
            cnt += (c & 0xFFFFu);
            er  += (c >> 16);
        }
        if (cnt > 0u) {
            atomicAdd(&g_su[j],  s);
            atomicAdd(&g_cnt[j], (float)cnt);
            atomicAdd(&g_err[j], (float)er);
        }
    }
}

__global__ void uce_finalize_kernel(float* __restrict__ out, float n) {
    if (threadIdx.x == 0 && blockIdx.x == 0) {
        float loss = 0.0f;
        for (int b = 0; b < NBINS; b++) {
            float c = g_cnt[b];
            float pi = c / n;
            float cnt = (c > 0.0f) ? c : 1.0f;
            float ub  = g_su[b]  / cnt;
            float eb  = g_err[b] / cnt;
            float inner = 2.0f * exp2f(-ub) - 1.0f;
            inner = (inner < 0.0f) ? 0.0f : inner;
            float r = 0.5f * (1.0f - sqrtf(inner));
            if (c > 0.0f) loss += fabsf(eb - r) * pi;
        }
        out[0] = loss;
    }
}

extern "C" void kernel_launch(void* const* d_in, const int* in_sizes, int n_in,
                              void* d_out, int out_size) {
    const float* logits = (const float*)d_in[0];
    const int*   labels = (const int*)d_in[1];
    float* out = (float*)d_out;

    int N = in_sizes[1];          // labels element count
    int P = N / 2;                // sample pairs

    zero_scratch_kernel<<<1, 32>>>();

    int blocks = (P + MAINTHREADS - 1) / MAINTHREADS;
    if (blocks > MAINBLOCKS) blocks = MAINBLOCKS;
    if (blocks < 1) blocks = 1;

    uce_main_kernel<<<blocks, MAINTHREADS>>>(
        (const float4*)logits, (const int2*)labels, P, N);

    uce_finalize_kernel<<<1, 32>>>(out, (float)N);
}